// round 1
// baseline (speedup 1.0000x reference)
#include <cuda_runtime.h>
#include <cstdint>
#include <cstddef>

// ---------------------------------------------------------------------------
// Problem dims
// ---------------------------------------------------------------------------
constexpr int   T_STEPS = 64;
constexpr int   BATCH   = 1024;
constexpr int   HID     = 512;
constexpr int   G3      = 3 * HID;                 // 1536
constexpr size_t NROWS  = (size_t)T_STEPS * BATCH; // 65536

// ---------------------------------------------------------------------------
// Scratch (device globals: allocation-free per harness rules)
// ---------------------------------------------------------------------------
__device__ float g_h   [NROWS * HID];   // ODE state H
__device__ float g_y   [NROWS * HID];   // RK4 stage input Y
__device__ float g_k   [NROWS * HID];   // stage derivative K
__device__ float g_acc [NROWS * HID];   // RK4 accumulator
__device__ float g_z1  [NROWS * HID];
__device__ float g_z2  [NROWS * HID];
__device__ float g_gi  [NROWS * G3];    // precomputed input gates
__device__ float g_gh  [BATCH * G3];    // per-step hidden gates
__device__ float g_hst [BATCH * HID];   // GRU hidden state
__device__ float g_beff[HID];           // effective bias for W1 (time folded)

// ---------------------------------------------------------------------------
// SGEMM: C[M,N] = A[M,K] @ B[K,N] + bias[N]   (all row-major, fp32)
// Requires M % BM == 0, N % BN == 0, K % 8 == 0 (true for all our shapes).
// ---------------------------------------------------------------------------
template<int BM, int BN, int TM, int TN>
__global__ void __launch_bounds__((BM/TM)*(BN/TN))
sgemm_bias(const float* __restrict__ A, const float* __restrict__ B,
           const float* __restrict__ bias, float* __restrict__ C,
           int M, int N, int K)
{
    constexpr int BK      = 8;
    constexpr int THREADS = (BM/TM)*(BN/TN);
    constexpr int A_PER   = BM*BK/THREADS;   // floats of A per thread per k-block (4 or 2)
    constexpr int B_PER   = BN*BK/THREADS;   // floats of B per thread per k-block (4 or 2)
    constexpr int A_TPR   = THREADS / BM;    // threads per A row

    __shared__ __align__(16) float As[BK][BM];
    __shared__ __align__(16) float Bs[BK][BN];

    const int  tid = threadIdx.x;
    const long bm  = (long)blockIdx.y * BM;
    const int  bn  = blockIdx.x * BN;
    constexpr int NTX = BN / TN;
    const int tx = tid % NTX;
    const int ty = tid / NTX;

    // A loader: thread -> (row, k-quad)
    const int ar = tid / A_TPR;
    const int ak = (tid % A_TPR) * A_PER;
    // B loader: thread -> (k-row, col-quad); BN/B_PER == 32 for both configs
    const int bkk = tid >> 5;
    const int bc  = (tid & 31) * B_PER;

    const float* Aptr = A + (bm + ar) * (size_t)K + ak;
    const float* Bptr = B + (size_t)bkk * N + bn + bc;

    float acc[TM][TN];
    #pragma unroll
    for (int i = 0; i < TM; i++)
        #pragma unroll
        for (int j = 0; j < TN; j++) acc[i][j] = 0.f;

    for (int k0 = 0; k0 < K; k0 += BK) {
        if constexpr (A_PER == 4) {
            float4 v = *reinterpret_cast<const float4*>(Aptr + k0);
            As[ak+0][ar] = v.x; As[ak+1][ar] = v.y;
            As[ak+2][ar] = v.z; As[ak+3][ar] = v.w;
        } else {
            float2 v = *reinterpret_cast<const float2*>(Aptr + k0);
            As[ak+0][ar] = v.x; As[ak+1][ar] = v.y;
        }
        if constexpr (B_PER == 4) {
            float4 v = *reinterpret_cast<const float4*>(Bptr + (size_t)k0 * N);
            *reinterpret_cast<float4*>(&Bs[bkk][bc]) = v;
        } else {
            float2 v = *reinterpret_cast<const float2*>(Bptr + (size_t)k0 * N);
            *reinterpret_cast<float2*>(&Bs[bkk][bc]) = v;
        }
        __syncthreads();

        #pragma unroll
        for (int kk = 0; kk < BK; kk++) {
            float a[TM], b[TN];
            #pragma unroll
            for (int v = 0; v < TM; v += 4)
                *reinterpret_cast<float4*>(&a[v]) =
                    *reinterpret_cast<const float4*>(&As[kk][ty*TM + v]);
            #pragma unroll
            for (int v = 0; v < TN; v += 4)
                *reinterpret_cast<float4*>(&b[v]) =
                    *reinterpret_cast<const float4*>(&Bs[kk][tx*TN + v]);
            #pragma unroll
            for (int i = 0; i < TM; i++)
                #pragma unroll
                for (int j = 0; j < TN; j++)
                    acc[i][j] = fmaf(a[i], b[j], acc[i][j]);
        }
        __syncthreads();
    }

    #pragma unroll
    for (int i = 0; i < TM; i++) {
        float* crow = C + (bm + ty*TM + i) * (size_t)N + bn + tx*TN;
        #pragma unroll
        for (int j = 0; j < TN; j++)
            crow[j] = acc[i][j] + bias[bn + tx*TN + j];
    }
}

// ---------------------------------------------------------------------------
// LayerNorm(512) + LeakyReLU(0.01) helper — block of 256 threads, 2 elems each
// ---------------------------------------------------------------------------
__device__ __forceinline__ float2 ln_lrelu_pair(float v0, float v1,
                                                const float* __restrict__ g,
                                                const float* __restrict__ b,
                                                int tid)
{
    __shared__ float red[8];
    float s = v0 + v1;
    #pragma unroll
    for (int o = 16; o > 0; o >>= 1) s += __shfl_xor_sync(0xffffffffu, s, o);
    if ((tid & 31) == 0) red[tid >> 5] = s;
    __syncthreads();
    float tot = 0.f;
    #pragma unroll
    for (int i = 0; i < 8; i++) tot += red[i];
    const float mean = tot * (1.0f / 512.0f);

    const float d0 = v0 - mean, d1 = v1 - mean;
    float q = d0*d0 + d1*d1;
    #pragma unroll
    for (int o = 16; o > 0; o >>= 1) q += __shfl_xor_sync(0xffffffffu, q, o);
    __syncthreads();                       // protect red[] reads above
    if ((tid & 31) == 0) red[tid >> 5] = q;
    __syncthreads();
    float vtot = 0.f;
    #pragma unroll
    for (int i = 0; i < 8; i++) vtot += red[i];
    const float rstd = rsqrtf(vtot * (1.0f / 512.0f) + 1e-5f);

    float y0 = fmaf(d0 * rstd, g[tid],       b[tid]);
    float y1 = fmaf(d1 * rstd, g[tid + 256], b[tid + 256]);
    y0 = (y0 > 0.f) ? y0 : 0.01f * y0;
    y1 = (y1 > 0.f) ? y1 : 0.01f * y1;
    return make_float2(y0, y1);
}

__global__ void ln_lrelu_kernel(float* __restrict__ X,
                                const float* __restrict__ g,
                                const float* __restrict__ b)
{
    const size_t row = blockIdx.x;
    const int tid = threadIdx.x;
    float* x = X + row * 512;
    float2 y = ln_lrelu_pair(x[tid], x[tid + 256], g, b, tid);
    x[tid]       = y.x;
    x[tid + 256] = y.y;
}

// obs -> hidden: Linear(8->512) + LN + LeakyReLU, one block per (t,b) row
__global__ void obs_embed_kernel(const float* __restrict__ xs,
                                 const float* __restrict__ W,
                                 const float* __restrict__ bias,
                                 const float* __restrict__ lg,
                                 const float* __restrict__ lb,
                                 float* __restrict__ H)
{
    const size_t row = blockIdx.x;
    const int tid = threadIdx.x;
    __shared__ float xv[8];
    if (tid < 8) xv[tid] = xs[row * 8 + tid];
    __syncthreads();

    float v0 = bias[tid], v1 = bias[tid + 256];
    #pragma unroll
    for (int k = 0; k < 8; k++) {
        v0 = fmaf(xv[k], W[k * 512 + tid],       v0);
        v1 = fmaf(xv[k], W[k * 512 + tid + 256], v1);
    }
    float2 y = ln_lrelu_pair(v0, v1, lg, lb, tid);
    H[row * 512 + tid]       = y.x;
    H[row * 512 + tid + 256] = y.y;
}

// effective bias for ode layer 1: beff[n] = b1[n] + t * W1[512, n]
__global__ void make_bias_kernel(float* __restrict__ beff,
                                 const float* __restrict__ b1,
                                 const float* __restrict__ w1_last, float t)
{
    int n = blockIdx.x * blockDim.x + threadIdx.x;
    if (n < 512) beff[n] = fmaf(t, w1_last[n], b1[n]);
}

// RK4 elementwise bookkeeping (float4-vectorized)
// mode 0: Acc = K;        Y = H + wy*K          (stage 1)
// mode 1: Acc += wacc*K;  Y = H + wy*K          (stages 2,3)
// mode 2: H  += (Acc + K) * (dt/6)              (stage 4; dt/6 = 1/24)
__global__ void rk4_update_kernel(const float* __restrict__ Ks,
                                  float* __restrict__ Acc,
                                  float* __restrict__ H,
                                  float* __restrict__ Y,
                                  float wacc, float wy, int mode)
{
    const size_t i = ((size_t)blockIdx.x * blockDim.x + threadIdx.x) * 4;
    float4 k = *reinterpret_cast<const float4*>(Ks + i);
    if (mode == 0) {
        *reinterpret_cast<float4*>(Acc + i) = k;
        float4 h = *reinterpret_cast<const float4*>(H + i);
        float4 y;
        y.x = fmaf(wy, k.x, h.x); y.y = fmaf(wy, k.y, h.y);
        y.z = fmaf(wy, k.z, h.z); y.w = fmaf(wy, k.w, h.w);
        *reinterpret_cast<float4*>(Y + i) = y;
    } else if (mode == 1) {
        float4 a = *reinterpret_cast<const float4*>(Acc + i);
        a.x = fmaf(wacc, k.x, a.x); a.y = fmaf(wacc, k.y, a.y);
        a.z = fmaf(wacc, k.z, a.z); a.w = fmaf(wacc, k.w, a.w);
        *reinterpret_cast<float4*>(Acc + i) = a;
        float4 h = *reinterpret_cast<const float4*>(H + i);
        float4 y;
        y.x = fmaf(wy, k.x, h.x); y.y = fmaf(wy, k.y, h.y);
        y.z = fmaf(wy, k.z, h.z); y.w = fmaf(wy, k.w, h.w);
        *reinterpret_cast<float4*>(Y + i) = y;
    } else {
        float4 a = *reinterpret_cast<const float4*>(Acc + i);
        float4 h = *reinterpret_cast<const float4*>(H + i);
        const float c = 1.0f / 24.0f;
        h.x = fmaf(a.x + k.x, c, h.x); h.y = fmaf(a.y + k.y, c, h.y);
        h.z = fmaf(a.z + k.z, c, h.z); h.w = fmaf(a.w + k.w, c, h.w);
        *reinterpret_cast<float4*>(H + i) = h;
    }
}

// GRU elementwise step (torch gate order r,z,n)
__global__ void gru_kernel(const float* __restrict__ GI,
                           const float* __restrict__ GH,
                           float* __restrict__ Hs)
{
    const int i   = blockIdx.x * blockDim.x + threadIdx.x;  // < 1024*512
    const int row = i >> 9;
    const int n   = i & 511;
    const float* gi = GI + (size_t)row * 1536;
    const float* gh = GH + (size_t)row * 1536;
    const float r  = 1.f / (1.f + expf(-(gi[n]        + gh[n])));
    const float z  = 1.f / (1.f + expf(-(gi[512 + n]  + gh[512 + n])));
    const float nn = tanhf(gi[1024 + n] + r * gh[1024 + n]);
    const float h  = Hs[i];
    Hs[i] = (1.f - z) * nn + z * h;
}

__global__ void zero_kernel(float* __restrict__ p, int n)
{
    int i = blockIdx.x * blockDim.x + threadIdx.x;
    if (i < n) p[i] = 0.f;
}

__global__ void copy_kernel(float* __restrict__ dst, const float* __restrict__ src, int n)
{
    int i = blockIdx.x * blockDim.x + threadIdx.x;
    if (i < n) dst[i] = src[i];
}

// ---------------------------------------------------------------------------
// Launch
// ---------------------------------------------------------------------------
extern "C" void kernel_launch(void* const* d_in, const int* in_sizes, int n_in,
                              void* d_out, int out_size)
{
    const float* xs       = (const float*)d_in[0];
    const float* obs_W    = (const float*)d_in[1];
    const float* obs_b    = (const float*)d_in[2];
    const float* obs_lg   = (const float*)d_in[3];
    const float* obs_lb   = (const float*)d_in[4];
    const float* ode_W1   = (const float*)d_in[5];   // [513, 512]
    const float* ode_b1   = (const float*)d_in[6];
    const float* ln1_g    = (const float*)d_in[7];
    const float* ln1_b    = (const float*)d_in[8];
    const float* ode_W2   = (const float*)d_in[9];
    const float* ode_b2   = (const float*)d_in[10];
    const float* ln2_g    = (const float*)d_in[11];
    const float* ln2_b    = (const float*)d_in[12];
    const float* ode_Wout = (const float*)d_in[13];
    const float* ode_bout = (const float*)d_in[14];
    const float* W_ih     = (const float*)d_in[15];  // [512, 1536]
    const float* b_ih     = (const float*)d_in[16];
    const float* W_hh     = (const float*)d_in[17];  // [512, 1536]
    const float* b_hh     = (const float*)d_in[18];

    float *p_h, *p_y, *p_k, *p_acc, *p_z1, *p_z2, *p_gi, *p_gh, *p_hst, *p_beff;
    cudaGetSymbolAddress((void**)&p_h,    g_h);
    cudaGetSymbolAddress((void**)&p_y,    g_y);
    cudaGetSymbolAddress((void**)&p_k,    g_k);
    cudaGetSymbolAddress((void**)&p_acc,  g_acc);
    cudaGetSymbolAddress((void**)&p_z1,   g_z1);
    cudaGetSymbolAddress((void**)&p_z2,   g_z2);
    cudaGetSymbolAddress((void**)&p_gi,   g_gi);
    cudaGetSymbolAddress((void**)&p_gh,   g_gh);
    cudaGetSymbolAddress((void**)&p_hst,  g_hst);
    cudaGetSymbolAddress((void**)&p_beff, g_beff);

    const int M = (int)NROWS;                       // 65536

    // 1. obs embedding for all timesteps (ODE initial conditions)
    obs_embed_kernel<<<M, 256>>>(xs, obs_W, obs_b, obs_lg, obs_lb, p_h);

    dim3 gBig(512  / 128, M / 128);                 // ODE GEMMs
    dim3 gGi (1536 / 128, M / 128);                 // gi GEMM
    dim3 gGru(1536 / 64,  BATCH / 64);              // GRU GEMM
    const int EW = (int)(NROWS * HID / (256 * 4));  // 32768 blocks, float4

    // 2. Batched RK4 over ALL timesteps at once (effective batch 65536)
    const float dt = 0.25f;
    const float toff[4] = {0.f, 0.125f, 0.125f, 0.25f};
    for (int s = 0; s < 4; s++) {
        const float t0 = (float)s * dt;
        for (int st = 0; st < 4; st++) {
            const float tt = t0 + toff[st];
            make_bias_kernel<<<2, 256>>>(p_beff, ode_b1, ode_W1 + 512 * 512, tt);
            const float* Ain = (st == 0) ? p_h : p_y;
            sgemm_bias<128,128,8,8><<<gBig, 256>>>(Ain, ode_W1, p_beff, p_z1, M, 512, 512);
            ln_lrelu_kernel<<<M, 256>>>(p_z1, ln1_g, ln1_b);
            sgemm_bias<128,128,8,8><<<gBig, 256>>>(p_z1, ode_W2, ode_b2, p_z2, M, 512, 512);
            ln_lrelu_kernel<<<M, 256>>>(p_z2, ln2_g, ln2_b);
            sgemm_bias<128,128,8,8><<<gBig, 256>>>(p_z2, ode_Wout, ode_bout, p_k, M, 512, 512);
            if      (st == 0) rk4_update_kernel<<<EW, 256>>>(p_k, p_acc, p_h, p_y, 1.f, 0.125f, 0);
            else if (st == 1) rk4_update_kernel<<<EW, 256>>>(p_k, p_acc, p_h, p_y, 2.f, 0.125f, 1);
            else if (st == 2) rk4_update_kernel<<<EW, 256>>>(p_k, p_acc, p_h, p_y, 2.f, 0.25f,  1);
            else              rk4_update_kernel<<<EW, 256>>>(p_k, p_acc, p_h, p_y, 1.f, 0.f,    2);
        }
    }

    // 3. Input gates for all timesteps in one GEMM
    sgemm_bias<128,128,8,8><<<gGi, 256>>>(p_h, W_ih, b_ih, p_gi, M, 1536, 512);

    // 4. Sequential GRU over T (only truly serial part)
    zero_kernel<<<(BATCH * HID) / 256, 256>>>(p_hst, BATCH * HID);
    for (int t = 0; t < T_STEPS; t++) {
        sgemm_bias<64,64,4,4><<<gGru, 256>>>(p_hst, W_hh, b_hh, p_gh, BATCH, 1536, 512);
        gru_kernel<<<(BATCH * HID) / 256, 256>>>(p_gi + (size_t)t * BATCH * G3, p_gh, p_hst);
    }

    // 5. Output
    copy_kernel<<<(BATCH * HID) / 256, 256>>>((float*)d_out, p_hst, BATCH * HID);
}

// round 3
// speedup vs baseline: 2.3517x; 2.3517x over previous
#include <cuda_runtime.h>
#include <cuda_bf16.h>
#include <cstdint>
#include <cstddef>

// ---------------------------------------------------------------------------
// Dims
// ---------------------------------------------------------------------------
constexpr int    T_STEPS = 64;
constexpr int    BATCH   = 1024;
constexpr int    HID     = 512;
constexpr int    G3      = 3 * HID;                  // 1536
constexpr size_t NROWS   = (size_t)T_STEPS * BATCH;  // 65536
constexpr int    KDIM    = 512;                      // K of every GEMM (per split segment)

// ---------------------------------------------------------------------------
// PTX helpers (arch-unconditional: sm_80-era instructions only)
// ---------------------------------------------------------------------------
__device__ __forceinline__ uint32_t smem_u32(const void* p) {
    uint32_t a;
    asm("{ .reg .u64 t; cvta.to.shared.u64 t, %1; cvt.u32.u64 %0, t; }"
        : "=r"(a) : "l"(p));
    return a;
}
#define CP16(s, g) \
    asm volatile("cp.async.cg.shared.global [%0], [%1], 16;\n" :: "r"(s), "l"(g) : "memory")
#define CP_COMMIT() asm volatile("cp.async.commit_group;\n" ::: "memory")

#define LDM_X4(r, addr)                                                         \
    asm volatile("ldmatrix.sync.aligned.m8n8.x4.shared.b16 {%0,%1,%2,%3}, [%4];" \
        : "=r"((r)[0]), "=r"((r)[1]), "=r"((r)[2]), "=r"((r)[3]) : "r"(addr))

#define MMA_BF16(d, a, b0, b1)                                                  \
    asm volatile("mma.sync.aligned.m16n8k16.row.col.f32.bf16.bf16.f32 "         \
        "{%0,%1,%2,%3}, {%4,%5,%6,%7}, {%8,%9}, {%0,%1,%2,%3};"                 \
        : "+f"((d)[0]), "+f"((d)[1]), "+f"((d)[2]), "+f"((d)[3])                \
        : "r"((a)[0]), "r"((a)[1]), "r"((a)[2]), "r"((a)[3]), "r"(b0), "r"(b1))

// ---------------------------------------------------------------------------
// Scratch (device globals: allocation-free)
// ---------------------------------------------------------------------------
__device__ float g_h  [NROWS * HID];
__device__ float g_acc[NROWS * HID];
__device__ float g_k  [NROWS * HID];
__device__ float g_z  [NROWS * HID];
__device__ float g_gi [NROWS * G3];
__device__ float g_gh [BATCH * G3];
__device__ float g_hst[BATCH * HID];
__device__ float g_beff[HID];

__device__ __nv_bfloat16 g_hhi[NROWS * HID], g_hlo[NROWS * HID];
__device__ __nv_bfloat16 g_xhi[NROWS * HID], g_xlo[NROWS * HID];
__device__ __nv_bfloat16 g_shi[BATCH * HID], g_slo[BATCH * HID];
__device__ __nv_bfloat16 g_w1hi[HID * HID],  g_w1lo[HID * HID];
__device__ __nv_bfloat16 g_w2hi[HID * HID],  g_w2lo[HID * HID];
__device__ __nv_bfloat16 g_wohi[HID * HID],  g_wolo[HID * HID];
__device__ __nv_bfloat16 g_wihi[G3 * HID],   g_wilo[G3 * HID];
__device__ __nv_bfloat16 g_whhi[G3 * HID],   g_whlo[G3 * HID];

// ---------------------------------------------------------------------------
// bf16x3-split GEMM via warp MMA (HMMA):
//   C[M,N] = (Ahi+Alo)[M,512] @ (Bhi+Blo)^T + bias,  B stored [N,512] bf16.
// Internally one K'=1536 loop: seg0 Ahi*Bhi, seg1 Alo*Bhi, seg2 Ahi*Blo.
// BM=BN=128, BK=32, 256 threads (8 warps: 2M x 4N, 64x32 per warp), 4 stages.
// grid = (N/128, M/128).
// ---------------------------------------------------------------------------
constexpr int STAGES      = 4;
constexpr int STAGE_BYTES = 16384;     // A 8KB + B 8KB
constexpr int GEMM_SMEM   = STAGES * STAGE_BYTES;   // 64KB
constexpr int NCHUNK      = 48;        // 3 * 512 / 32

// smem tile layout: row-major [128][32] bf16, 64B rows, 16B-chunk swizzle
// chunk c (0..3) at row r stored at chunk (c ^ ((r>>1)&3)).
__device__ __forceinline__ void g2s_stage(uint32_t sbase,
    const __nv_bfloat16* __restrict__ A, const __nv_bfloat16* __restrict__ B,
    size_t bm, size_t bn, int kloc, int tid)
{
    const int c  = tid & 3;
    const int r0 = tid >> 2;                        // 0..63
    #pragma unroll
    for (int i = 0; i < 2; i++) {
        const int r = r0 + i * 64;
        const uint32_t dst = sbase + (uint32_t)(r * 64 + 16 * (c ^ ((r >> 1) & 3)));
        CP16(dst,        A + (bm + r) * KDIM + kloc + c * 8);
        CP16(dst + 8192, B + (bn + r) * KDIM + kloc + c * 8);
    }
    CP_COMMIT();
}

__global__ void __launch_bounds__(256)
gemm_split3(const __nv_bfloat16* __restrict__ Ahi, const __nv_bfloat16* __restrict__ Alo,
            const __nv_bfloat16* __restrict__ Bhi, const __nv_bfloat16* __restrict__ Blo,
            const float* __restrict__ bias, float* __restrict__ C, int N)
{
    extern __shared__ char smem[];
    const uint32_t sb   = smem_u32(smem);
    const int tid  = threadIdx.x;
    const int lane = tid & 31;
    const int wid  = tid >> 5;
    const int wm   = (wid >> 2) * 64;               // warp M offset (0/64)
    const int wn   = (wid & 3) * 32;                // warp N offset (0/32/64/96)
    const size_t bm = (size_t)blockIdx.y * 128;
    const size_t bn = (size_t)blockIdx.x * 128;

    float acc[4][4][4];
    #pragma unroll
    for (int i = 0; i < 4; i++)
        #pragma unroll
        for (int j = 0; j < 4; j++)
            #pragma unroll
            for (int v = 0; v < 4; v++) acc[i][j][v] = 0.f;

    // split-segment selectors
    auto Aseg = [&](int kc) { return ((kc >> 4) == 1) ? Alo : Ahi; };
    auto Bseg = [&](int kc) { return ((kc >> 4) == 2) ? Blo : Bhi; };

    #pragma unroll
    for (int kc = 0; kc < STAGES - 1; kc++)
        g2s_stage(sb + kc * STAGE_BYTES, Aseg(kc), Bseg(kc), bm, bn, (kc & 15) * 32, tid);

    #pragma unroll 1
    for (int kc = 0; kc < NCHUNK; kc++) {
        asm volatile("cp.async.wait_group 2;" ::: "memory");
        __syncthreads();
        if (kc + 3 < NCHUNK) {
            const int kn = kc + 3;
            g2s_stage(sb + (kn & 3) * STAGE_BYTES, Aseg(kn), Bseg(kn), bm, bn,
                      (kn & 15) * 32, tid);
        }
        const uint32_t st = sb + (kc & 3) * STAGE_BYTES;

        #pragma unroll
        for (int s = 0; s < 2; s++) {               // two k16 steps per 32-chunk
            uint32_t a[4][4], bfr[2][4];
            #pragma unroll
            for (int mf = 0; mf < 4; mf++) {
                const int ar = wm + mf * 16 + (lane & 15);
                const int ac = s * 2 + (lane >> 4);
                LDM_X4(a[mf], st + (uint32_t)(ar * 64 + 16 * (ac ^ ((ar >> 1) & 3))));
            }
            #pragma unroll
            for (int nf16 = 0; nf16 < 2; nf16++) {
                const int br = wn + nf16 * 16 + (lane & 7) + ((lane >> 4) & 1) * 8;
                const int bc = s * 2 + ((lane >> 3) & 1);
                LDM_X4(bfr[nf16],
                       st + 8192 + (uint32_t)(br * 64 + 16 * (bc ^ ((br >> 1) & 3))));
            }
            #pragma unroll
            for (int mf = 0; mf < 4; mf++)
                #pragma unroll
                for (int nf = 0; nf < 4; nf++)
                    MMA_BF16(acc[mf][nf], a[mf],
                             bfr[nf >> 1][(nf & 1) * 2], bfr[nf >> 1][(nf & 1) * 2 + 1]);
        }
        __syncthreads();
    }

    // Epilogue: bias add, fp32 store
    #pragma unroll
    for (int mf = 0; mf < 4; mf++) {
        const size_t r0 = bm + wm + mf * 16 + (lane >> 2);
        #pragma unroll
        for (int nf = 0; nf < 4; nf++) {
            const int col = wn + nf * 8 + (lane & 3) * 2;
            const float b0 = bias[bn + col], b1 = bias[bn + col + 1];
            float2 v0 = make_float2(acc[mf][nf][0] + b0, acc[mf][nf][1] + b1);
            float2 v1 = make_float2(acc[mf][nf][2] + b0, acc[mf][nf][3] + b1);
            *reinterpret_cast<float2*>(C + r0 * N + bn + col)       = v0;
            *reinterpret_cast<float2*>(C + (r0 + 8) * N + bn + col) = v1;
        }
    }
}

// ---------------------------------------------------------------------------
// bf16 split helpers
// ---------------------------------------------------------------------------
__device__ __forceinline__ void split1(float v, __nv_bfloat16& hi, __nv_bfloat16& lo) {
    hi = __float2bfloat16(v);
    lo = __float2bfloat16(v - __bfloat162float(hi));
}
__device__ __forceinline__ void split_store2(__nv_bfloat16* Hi, __nv_bfloat16* Lo,
                                             size_t i, float a, float b) {
    __nv_bfloat162 h, l;
    split1(a, h.x, l.x); split1(b, h.y, l.y);
    *reinterpret_cast<__nv_bfloat162*>(Hi + i) = h;
    *reinterpret_cast<__nv_bfloat162*>(Lo + i) = l;
}

__device__ __forceinline__ float block_sum512(float x, float* red, int tid) {
    #pragma unroll
    for (int o = 16; o > 0; o >>= 1) x += __shfl_xor_sync(0xffffffffu, x, o);
    __syncthreads();
    if ((tid & 31) == 0) red[tid >> 5] = x;
    __syncthreads();
    float t = 0.f;
    #pragma unroll
    for (int i = 0; i < 8; i++) t += red[i];
    return t;
}

// LN(512)+LeakyReLU, fp32 in -> bf16 split out. One block per row, 256 thr.
__global__ void ln_lrelu_split(const float* __restrict__ Z,
                               const float* __restrict__ g, const float* __restrict__ b,
                               __nv_bfloat16* __restrict__ Xhi, __nv_bfloat16* __restrict__ Xlo)
{
    __shared__ float red[8];
    const size_t row = blockIdx.x;
    const int tid = threadIdx.x;
    const int c = 2 * tid;
    float2 v = *reinterpret_cast<const float2*>(Z + row * 512 + c);
    const float mean = block_sum512(v.x + v.y, red, tid) * (1.f / 512.f);
    const float d0 = v.x - mean, d1 = v.y - mean;
    const float rstd = rsqrtf(block_sum512(d0 * d0 + d1 * d1, red, tid) * (1.f / 512.f) + 1e-5f);
    const float2 gg = *reinterpret_cast<const float2*>(g + c);
    const float2 bb = *reinterpret_cast<const float2*>(b + c);
    float y0 = fmaf(d0 * rstd, gg.x, bb.x);
    float y1 = fmaf(d1 * rstd, gg.y, bb.y);
    y0 = (y0 > 0.f) ? y0 : 0.01f * y0;
    y1 = (y1 > 0.f) ? y1 : 0.01f * y1;
    split_store2(Xhi, Xlo, row * 512 + c, y0, y1);
}

// obs -> hidden: Linear(8->512)+LN+LeakyReLU; writes fp32 H + split
__global__ void obs_embed(const float* __restrict__ xs, const float* __restrict__ W,
                          const float* __restrict__ bias,
                          const float* __restrict__ lg, const float* __restrict__ lb,
                          float* __restrict__ H,
                          __nv_bfloat16* __restrict__ Hhi, __nv_bfloat16* __restrict__ Hlo)
{
    __shared__ float xv[8];
    __shared__ float red[8];
    const size_t row = blockIdx.x;
    const int tid = threadIdx.x;
    const int c = 2 * tid;
    if (tid < 8) xv[tid] = xs[row * 8 + tid];
    __syncthreads();
    float2 v = *reinterpret_cast<const float2*>(bias + c);
    #pragma unroll
    for (int k = 0; k < 8; k++) {
        float2 w = *reinterpret_cast<const float2*>(W + k * 512 + c);
        v.x = fmaf(xv[k], w.x, v.x);
        v.y = fmaf(xv[k], w.y, v.y);
    }
    const float mean = block_sum512(v.x + v.y, red, tid) * (1.f / 512.f);
    const float d0 = v.x - mean, d1 = v.y - mean;
    const float rstd = rsqrtf(block_sum512(d0 * d0 + d1 * d1, red, tid) * (1.f / 512.f) + 1e-5f);
    const float2 gg = *reinterpret_cast<const float2*>(lg + c);
    const float2 bb = *reinterpret_cast<const float2*>(lb + c);
    float y0 = fmaf(d0 * rstd, gg.x, bb.x);
    float y1 = fmaf(d1 * rstd, gg.y, bb.y);
    y0 = (y0 > 0.f) ? y0 : 0.01f * y0;
    y1 = (y1 > 0.f) ? y1 : 0.01f * y1;
    *reinterpret_cast<float2*>(H + row * 512 + c) = make_float2(y0, y1);
    split_store2(Hhi, Hlo, row * 512 + c, y0, y1);
}

__global__ void make_bias_kernel(float* __restrict__ beff, const float* __restrict__ b1,
                                 const float* __restrict__ w1_last, float t)
{
    int n = blockIdx.x * blockDim.x + threadIdx.x;
    if (n < 512) beff[n] = fmaf(t, w1_last[n], b1[n]);
}

// RK4 bookkeeping. mode0: Acc=K, Y=H+wy*K (split). mode1: Acc+=wacc*K, Y split.
// mode2: H += (Acc+K)/24, write H fp32 + split.
__global__ void rk4_update(const float* __restrict__ Ks, float* __restrict__ Acc,
                           float* __restrict__ H,
                           __nv_bfloat16* __restrict__ Yhi, __nv_bfloat16* __restrict__ Ylo,
                           float wacc, float wy, int mode)
{
    const size_t i = ((size_t)blockIdx.x * blockDim.x + threadIdx.x) * 4;
    float4 k = *reinterpret_cast<const float4*>(Ks + i);
    float4 h = *reinterpret_cast<const float4*>(H + i);
    if (mode == 0) {
        *reinterpret_cast<float4*>(Acc + i) = k;
        split_store2(Yhi, Ylo, i,     fmaf(wy, k.x, h.x), fmaf(wy, k.y, h.y));
        split_store2(Yhi, Ylo, i + 2, fmaf(wy, k.z, h.z), fmaf(wy, k.w, h.w));
    } else if (mode == 1) {
        float4 a = *reinterpret_cast<const float4*>(Acc + i);
        a.x = fmaf(wacc, k.x, a.x); a.y = fmaf(wacc, k.y, a.y);
        a.z = fmaf(wacc, k.z, a.z); a.w = fmaf(wacc, k.w, a.w);
        *reinterpret_cast<float4*>(Acc + i) = a;
        split_store2(Yhi, Ylo, i,     fmaf(wy, k.x, h.x), fmaf(wy, k.y, h.y));
        split_store2(Yhi, Ylo, i + 2, fmaf(wy, k.z, h.z), fmaf(wy, k.w, h.w));
    } else {
        float4 a = *reinterpret_cast<const float4*>(Acc + i);
        const float cc = 1.0f / 24.0f;
        h.x = fmaf(a.x + k.x, cc, h.x); h.y = fmaf(a.y + k.y, cc, h.y);
        h.z = fmaf(a.z + k.z, cc, h.z); h.w = fmaf(a.w + k.w, cc, h.w);
        *reinterpret_cast<float4*>(H + i) = h;
        split_store2(Yhi, Ylo, i,     h.x, h.y);
        split_store2(Yhi, Ylo, i + 2, h.z, h.w);
    }
}

// GRU elementwise (torch gate order r,z,n); updates fp32 h + split
__global__ void gru_step(const float* __restrict__ GI, const float* __restrict__ GH,
                         float* __restrict__ Hs,
                         __nv_bfloat16* __restrict__ Shi, __nv_bfloat16* __restrict__ Slo)
{
    const int i   = blockIdx.x * blockDim.x + threadIdx.x;
    const int row = i >> 9;
    const int n   = i & 511;
    const float* gi = GI + (size_t)row * 1536;
    const float* gh = GH + (size_t)row * 1536;
    const float r  = 1.f / (1.f + expf(-(gi[n]       + gh[n])));
    const float z  = 1.f / (1.f + expf(-(gi[512 + n] + gh[512 + n])));
    const float nn = tanhf(gi[1024 + n] + r * gh[1024 + n]);
    const float h  = (1.f - z) * nn + z * Hs[i];
    Hs[i] = h;
    split1(h, Shi[i], Slo[i]);
}

// W[K,N] (fp32 row-major) -> Whi/Wlo[N,K] bf16 split (transposed)
__global__ void wsplit(const float* __restrict__ W,
                       __nv_bfloat16* __restrict__ Whi, __nv_bfloat16* __restrict__ Wlo,
                       int K, int N)
{
    int idx = blockIdx.x * blockDim.x + threadIdx.x;
    if (idx >= K * N) return;
    int k = idx / N, n = idx % N;
    float v = W[idx];
    __nv_bfloat16 hi, lo;
    split1(v, hi, lo);
    Whi[(size_t)n * K + k] = hi;
    Wlo[(size_t)n * K + k] = lo;
}

__global__ void zero_state(float* __restrict__ h,
                           __nv_bfloat16* __restrict__ hi, __nv_bfloat16* __restrict__ lo)
{
    int i = blockIdx.x * blockDim.x + threadIdx.x;
    h[i] = 0.f;
    hi[i] = __float2bfloat16(0.f);
    lo[i] = __float2bfloat16(0.f);
}

__global__ void copy_kernel(float* __restrict__ dst, const float* __restrict__ src)
{
    int i = blockIdx.x * blockDim.x + threadIdx.x;
    dst[i] = src[i];
}

// ---------------------------------------------------------------------------
// Launch
// ---------------------------------------------------------------------------
extern "C" void kernel_launch(void* const* d_in, const int* in_sizes, int n_in,
                              void* d_out, int out_size)
{
    const float* xs       = (const float*)d_in[0];
    const float* obs_W    = (const float*)d_in[1];
    const float* obs_b    = (const float*)d_in[2];
    const float* obs_lg   = (const float*)d_in[3];
    const float* obs_lb   = (const float*)d_in[4];
    const float* ode_W1   = (const float*)d_in[5];   // [513, 512]
    const float* ode_b1   = (const float*)d_in[6];
    const float* ln1_g    = (const float*)d_in[7];
    const float* ln1_b    = (const float*)d_in[8];
    const float* ode_W2   = (const float*)d_in[9];
    const float* ode_b2   = (const float*)d_in[10];
    const float* ln2_g    = (const float*)d_in[11];
    const float* ln2_b    = (const float*)d_in[12];
    const float* ode_Wout = (const float*)d_in[13];
    const float* ode_bout = (const float*)d_in[14];
    const float* W_ih     = (const float*)d_in[15];  // [512, 1536]
    const float* b_ih     = (const float*)d_in[16];
    const float* W_hh     = (const float*)d_in[17];
    const float* b_hh     = (const float*)d_in[18];

    float *p_h, *p_acc, *p_k, *p_z, *p_gi, *p_gh, *p_hst, *p_beff;
    __nv_bfloat16 *p_hhi, *p_hlo, *p_xhi, *p_xlo, *p_shi, *p_slo;
    __nv_bfloat16 *w1h, *w1l, *w2h, *w2l, *woh, *wol, *wih, *wil, *whh, *whl;
    cudaGetSymbolAddress((void**)&p_h,    g_h);
    cudaGetSymbolAddress((void**)&p_acc,  g_acc);
    cudaGetSymbolAddress((void**)&p_k,    g_k);
    cudaGetSymbolAddress((void**)&p_z,    g_z);
    cudaGetSymbolAddress((void**)&p_gi,   g_gi);
    cudaGetSymbolAddress((void**)&p_gh,   g_gh);
    cudaGetSymbolAddress((void**)&p_hst,  g_hst);
    cudaGetSymbolAddress((void**)&p_beff, g_beff);
    cudaGetSymbolAddress((void**)&p_hhi,  g_hhi);
    cudaGetSymbolAddress((void**)&p_hlo,  g_hlo);
    cudaGetSymbolAddress((void**)&p_xhi,  g_xhi);
    cudaGetSymbolAddress((void**)&p_xlo,  g_xlo);
    cudaGetSymbolAddress((void**)&p_shi,  g_shi);
    cudaGetSymbolAddress((void**)&p_slo,  g_slo);
    cudaGetSymbolAddress((void**)&w1h,    g_w1hi);
    cudaGetSymbolAddress((void**)&w1l,    g_w1lo);
    cudaGetSymbolAddress((void**)&w2h,    g_w2hi);
    cudaGetSymbolAddress((void**)&w2l,    g_w2lo);
    cudaGetSymbolAddress((void**)&woh,    g_wohi);
    cudaGetSymbolAddress((void**)&wol,    g_wolo);
    cudaGetSymbolAddress((void**)&wih,    g_wihi);
    cudaGetSymbolAddress((void**)&wil,    g_wilo);
    cudaGetSymbolAddress((void**)&whh,    g_whhi);
    cudaGetSymbolAddress((void**)&whl,    g_whlo);

    cudaFuncSetAttribute(gemm_split3, cudaFuncAttributeMaxDynamicSharedMemorySize, GEMM_SMEM);

    const int M = (int)NROWS;

    // Weight prep: transpose + bf16 split (W1 uses only its first 512 rows)
    wsplit<<<(512 * 512) / 256, 256>>>(ode_W1,   w1h, w1l, 512, 512);
    wsplit<<<(512 * 512) / 256, 256>>>(ode_W2,   w2h, w2l, 512, 512);
    wsplit<<<(512 * 512) / 256, 256>>>(ode_Wout, woh, wol, 512, 512);
    wsplit<<<(512 * 1536) / 256, 256>>>(W_ih, wih, wil, 512, 1536);
    wsplit<<<(512 * 1536) / 256, 256>>>(W_hh, whh, whl, 512, 1536);

    // obs embedding
    obs_embed<<<M, 256>>>(xs, obs_W, obs_b, obs_lg, obs_lb, p_h, p_hhi, p_hlo);

    dim3 gBig(512 / 128,  M / 128);       // (4, 512)
    dim3 gGi (1536 / 128, M / 128);       // (12, 512)
    dim3 gGru(1536 / 128, BATCH / 128);   // (12, 8)
    const int EW = (int)(NROWS * HID / (256 * 4));

    // Batched RK4 over ALL timesteps (effective batch 65536)
    const float dt = 0.25f;
    const float toff[4] = {0.f, 0.125f, 0.125f, 0.25f};
    for (int s = 0; s < 4; s++) {
        const float t0 = (float)s * dt;
        for (int st = 0; st < 4; st++) {
            make_bias_kernel<<<2, 256>>>(p_beff, ode_b1, ode_W1 + 512 * 512, t0 + toff[st]);
            const __nv_bfloat16* Ah = (st == 0) ? p_hhi : p_xhi;
            const __nv_bfloat16* Al = (st == 0) ? p_hlo : p_xlo;
            gemm_split3<<<gBig, 256, GEMM_SMEM>>>(Ah, Al, w1h, w1l, p_beff, p_z, 512);
            ln_lrelu_split<<<M, 256>>>(p_z, ln1_g, ln1_b, p_xhi, p_xlo);
            gemm_split3<<<gBig, 256, GEMM_SMEM>>>(p_xhi, p_xlo, w2h, w2l, ode_b2, p_z, 512);
            ln_lrelu_split<<<M, 256>>>(p_z, ln2_g, ln2_b, p_xhi, p_xlo);
            gemm_split3<<<gBig, 256, GEMM_SMEM>>>(p_xhi, p_xlo, woh, wol, ode_bout, p_k, 512);
            if      (st == 0) rk4_update<<<EW, 256>>>(p_k, p_acc, p_h, p_xhi, p_xlo, 1.f, 0.125f, 0);
            else if (st == 1) rk4_update<<<EW, 256>>>(p_k, p_acc, p_h, p_xhi, p_xlo, 2.f, 0.125f, 1);
            else if (st == 2) rk4_update<<<EW, 256>>>(p_k, p_acc, p_h, p_xhi, p_xlo, 2.f, 0.25f,  1);
            else              rk4_update<<<EW, 256>>>(p_k, p_acc, p_h, p_hhi, p_hlo, 1.f, 0.f,    2);
        }
    }

    // Input gates for all timesteps in one GEMM
    gemm_split3<<<gGi, 256, GEMM_SMEM>>>(p_hhi, p_hlo, wih, wil, b_ih, p_gi, 1536);

    // Sequential GRU
    zero_state<<<(BATCH * HID) / 256, 256>>>(p_hst, p_shi, p_slo);
    for (int t = 0; t < T_STEPS; t++) {
        gemm_split3<<<gGru, 256, GEMM_SMEM>>>(p_shi, p_slo, whh, whl, b_hh, p_gh, 1536);
        gru_step<<<(BATCH * HID) / 256, 256>>>(p_gi + (size_t)t * BATCH * G3, p_gh,
                                               p_hst, p_shi, p_slo);
    }

    copy_kernel<<<(BATCH * HID) / 256, 256>>>((float*)d_out, p_hst);
}